// round 15
// baseline (speedup 1.0000x reference)
#include <cuda_runtime.h>
#include <cuda_fp16.h>
#include <cstdint>

#define TT 256
#define BB 512
#define FF 64
#define UU 128
#define NG 512           // 4*U
#define TB (TT*BB)       // 131072

// ---------- static device scratch (no allocation) ----------
__device__ __half g_xz [(size_t)TB * NG];   // xz fp16, gate-interleaved [m][u*4+g]
__device__ __half g_hs [(size_t)TB * UU];   // layer-1 hidden states [t][b][u]
__device__ float  g_hlast[BB * UU];         // layer-2 final h

// ---------- helpers ----------
__device__ __forceinline__ void mma16816(float* d, const uint32_t* a, uint32_t b0, uint32_t b1) {
    asm volatile(
        "mma.sync.aligned.m16n8k16.row.col.f32.f16.f16.f32 "
        "{%0,%1,%2,%3}, {%4,%5,%6,%7}, {%8,%9}, {%0,%1,%2,%3};"
        : "+f"(d[0]), "+f"(d[1]), "+f"(d[2]), "+f"(d[3])
        : "r"(a[0]), "r"(a[1]), "r"(a[2]), "r"(a[3]), "r"(b0), "r"(b1));
}
__device__ __forceinline__ void ldsm4(uint32_t* a, const __half* p) {
    uint32_t addr = (uint32_t)__cvta_generic_to_shared(p);
    asm volatile("ldmatrix.sync.aligned.m8n8.x4.shared.b16 {%0,%1,%2,%3}, [%4];"
                 : "=r"(a[0]), "=r"(a[1]), "=r"(a[2]), "=r"(a[3]) : "r"(addr));
}
__device__ __forceinline__ float tanha(float x) {
    float r;
    asm("tanh.approx.f32 %0, %1;" : "=f"(r) : "f"(x));
    return r;
}
__device__ __forceinline__ float sigm(float x) {
    return fmaf(0.5f, tanha(0.5f * x), 0.5f);
}

// ---------- GEMM: out16[M][perm(512)] = A @ W(fp32->fp16) + bias ----------
// Physical output col P holds logical gate-col l = (P&3)*128 + (P>>2), i.e.
// out[m][u*4+g]. Permutation applied at Wp/bias GATHER (free); stores remain
// coalesced half2. Software-pipelined: double-buffered As, ONE barrier/tile.
// DX=true: A is raw x fp32 [b][t][f] (K=64).
template <int K, bool DX>
__global__ void __launch_bounds__(256, 2)
k_gemm(const void* __restrict__ Av, const float* __restrict__ Wg,
       const float* __restrict__ bias, __half* __restrict__ out, int Mtiles) {
    extern __shared__ char sm[];
    const int NT = 128, LDW = 136, ldA = K + 8;
    uint32_t* Wp = (uint32_t*)sm;                                  // [K/2][136] half2
    __half*   As = (__half*)(sm + (K / 2) * LDW * 4);              // [2][64][K+8]
    const int ABUF = 64 * ldA;
    int tid = threadIdx.x, w = tid >> 5, lane = tid & 31;
    int n0 = (blockIdx.x & 3) * NT;
    int tile0 = blockIdx.x >> 2, tstep = gridDim.x >> 2;

    for (int i = tid; i < (K / 2) * NT; i += 256) {
        int kk = i >> 7, nl = i & 127;
        int P = n0 + nl;
        int l = (P & 3) * 128 + (P >> 2);        // gate-interleave permutation
        __half2 h2 = __floats2half2_rn(Wg[(size_t)(2 * kk) * NG + l],
                                       Wg[(size_t)(2 * kk + 1) * NG + l]);
        Wp[kk * LDW + nl] = *(uint32_t*)&h2;
    }

    float4 stg[4];
    auto ldtile = [&](int m0) {
#pragma unroll
        for (int s = 0; s < 4; s++) {
            int i = tid + 256 * s;
            int r = i >> 4;
            if (DX) {
                int c = (i & 15) * 4;
                int m = m0 + r, t = m >> 9, b = m & 511;
                stg[s] = *(const float4*)&((const float*)Av)[((size_t)(b << 8 | t)) * FF + c];
            } else {
                int c = (i & 15) * 8;
                stg[s] = *(const float4*)&((const __half*)Av)[(size_t)(m0 + r) * K + c];
            }
        }
    };
    auto sttile = [&](int buf) {
#pragma unroll
        for (int s = 0; s < 4; s++) {
            int i = tid + 256 * s;
            int r = i >> 4;
            if (DX) {
                int c = (i & 15) * 4;
                *(__half2*)&As[buf * ABUF + r * ldA + c]     = __floats2half2_rn(stg[s].x, stg[s].y);
                *(__half2*)&As[buf * ABUF + r * ldA + c + 2] = __floats2half2_rn(stg[s].z, stg[s].w);
            } else {
                int c = (i & 15) * 8;
                *(float4*)&As[buf * ABUF + r * ldA + c] = stg[s];
            }
        }
    };

    int cur = 0;
    ldtile(tile0 * 64);
    sttile(0);
    __syncthreads();

    for (int tile = tile0; tile < Mtiles; tile += tstep) {
        int m0 = tile * 64;
        bool havenext = (tile + tstep < Mtiles);
        if (havenext) ldtile((tile + tstep) * 64);

        float acc[4][2][4];
#pragma unroll
        for (int mt = 0; mt < 4; mt++)
#pragma unroll
            for (int nt = 0; nt < 2; nt++)
#pragma unroll
                for (int q = 0; q < 4; q++) acc[mt][nt][q] = 0.f;

        const __half* Ac = As + cur * ABUF;
#pragma unroll
        for (int kt = 0; kt < K / 16; kt++) {
            uint32_t a[4][4];
#pragma unroll
            for (int mt = 0; mt < 4; mt++) {
                int row = mt * 16 + (lane & 15);
                int col = kt * 16 + (lane >> 4) * 8;
                ldsm4(a[mt], &Ac[row * ldA + col]);
            }
            int c4 = lane & 3;
#pragma unroll
            for (int nt = 0; nt < 2; nt++) {
                int nl = w * 16 + nt * 8 + (lane >> 2);
                uint32_t b0 = Wp[(kt * 8 + c4) * LDW + nl];
                uint32_t b1 = Wp[(kt * 8 + 4 + c4) * LDW + nl];
#pragma unroll
                for (int mt = 0; mt < 4; mt++) mma16816(acc[mt][nt], a[mt], b0, b1);
            }
        }

#pragma unroll
        for (int mt = 0; mt < 4; mt++) {
            int r0 = m0 + mt * 16 + (lane >> 2);
#pragma unroll
            for (int nt = 0; nt < 2; nt++) {
                int cc = n0 + w * 16 + nt * 8 + (lane & 3) * 2;
                int l0 = (cc & 3) * 128 + (cc >> 2);
                int l1 = ((cc + 1) & 3) * 128 + ((cc + 1) >> 2);
                float bb0 = __ldg(&bias[l0]), bb1 = __ldg(&bias[l1]);
                *(__half2*)&out[(size_t)r0 * NG + cc] =
                    __floats2half2_rn(acc[mt][nt][0] + bb0, acc[mt][nt][1] + bb1);
                *(__half2*)&out[(size_t)(r0 + 8) * NG + cc] =
                    __floats2half2_rn(acc[mt][nt][2] + bb0, acc[mt][nt][3] + bb1);
            }
        }

        if (havenext) sttile(cur ^ 1);
        __syncthreads();
        cur ^= 1;
    }
}

// ---------- LSTM recurrence ----------
// 128 CTAs x 4 batches, 512 threads (16 warps). Warp w owns units [w*8, w*8+8)
// with 2 m16-tiles: tile mt -> gates {2mt, 2mt+1}. Split even/odd-kt
// accumulators. n>=4 B-fragments are structurally zero -> lanes 16-31 skip the
// hp LDS entirely (halves smem crossbar traffic). Per-warp kt rotation
// de-phases the 16 warps' post-barrier LDS/tensor bursts. ONE barrier/step.
template <int LAYER>
__global__ void __launch_bounds__(512, 1)
k_rnn(const float* __restrict__ Urec) {
    extern __shared__ char sm[];
    __half* As = (__half*)sm;                        // [512][136] = 139264 B
    char*   hp = sm + 512 * 136 * 2;                 // 2 phases x 2048 B
    const int th = threadIdx.x, w = th >> 5, lane = th & 31;
    const int b0 = blockIdx.x * 4;

    // stage permuted U^T: row = w*32 + mt*16 + sub*8 + r -> G = (2mt+sub)*128 + w*8 + r
    for (int i = th; i < 512 * 128; i += 512) {
        int row = i >> 7, k = i & 127;
        int ww = row >> 5, mt = (row >> 4) & 1, sub = (row >> 3) & 1, r = row & 7;
        int G = (2 * mt + sub) * 128 + ww * 8 + r;
        As[row * 136 + k] = __float2half(Urec[(size_t)k * NG + G]);
    }
    for (int i = th; i < 1024; i += 512) ((uint32_t*)hp)[i] = 0u;
    __syncthreads();

    uint32_t ua[2][8][4];
#pragma unroll
    for (int mt = 0; mt < 2; mt++) {
        int row = w * 32 + mt * 16 + (lane & 15);
#pragma unroll
        for (int kt = 0; kt < 8; kt++)
            ldsm4(ua[mt][kt], &As[row * 136 + kt * 16 + (lane >> 4) * 8]);
    }
    __syncthreads();

    const int q  = lane & 3, r8 = lane >> 2;
    const int ut = w * 8 + r8;                      // this lane's unit
    const int srcl = (lane & 28) | (q >> 1);        // shfl source lane
    const int hoff = (ut >> 4) * 256 + ((ut & 7) >> 1) * 64 + q * 8
                   + ((ut >> 3) & 1) * 4 + (ut & 1) * 2;
    const int krot = (w & 3) << 1;                  // even rotation: parity preserved
    const bool bload = (lane < 16);                 // n>=4 fragments are zero

    // xz gate-interleaved: one 8-byte load = 4 gates (i,f,g,o) fp16
    uint2 xc = *(const uint2*)&g_xz[((size_t)(b0 + q)) * NG + ut * 4];
    float cst = 0.f;
    int ph = 0;

    for (int t = 0; t < TT; t++) {
        // ---- mma: z = U^T @ h^T (reads hp[ph]); even/odd split chains ----
        float ae[2][4], ao[2][4];
#pragma unroll
        for (int mt = 0; mt < 2; mt++)
#pragma unroll
            for (int j = 0; j < 4; j++) { ae[mt][j] = 0.f; ao[mt][j] = 0.f; }
        const char* hpc = hp + ph * 2048;
#pragma unroll
        for (int kt = 0; kt < 8; kt++) {
            int ktr = (kt + krot) & 7;              // de-phase warps
            uint2 bf = make_uint2(0u, 0u);
            if (bload)
                bf = *(const uint2*)(hpc + ktr * 256 + (lane & 3) * 64 + (lane >> 2) * 8);
            float* d0 = (ktr & 1) ? ao[0] : ae[0];
            float* d1 = (ktr & 1) ? ao[1] : ae[1];
            mma16816(d0, ua[0][ktr], bf.x, bf.y);
            mma16816(d1, ua[1][ktr], bf.x, bf.y);
        }
        float acc[2][4];
#pragma unroll
        for (int mt = 0; mt < 2; mt++)
#pragma unroll
            for (int j = 0; j < 4; j++) acc[mt][j] = ae[mt][j] + ao[mt][j];

        // prefetch next step's xz (one 8B load)
        uint2 xn = xc;
        if (t + 1 < TT)
            xn = *(const uint2*)&g_xz[((size_t)(t + 1) * BB + b0 + q) * NG + ut * 4];

        // ---- gate extraction: 8 shfl + 4 selects ----
        float va, vb, iz, fz, gz, oz;
        va = __shfl_sync(0xffffffffu, acc[0][0], srcl);
        vb = __shfl_sync(0xffffffffu, acc[0][1], srcl);
        iz = (q & 1) ? vb : va;
        va = __shfl_sync(0xffffffffu, acc[0][2], srcl);
        vb = __shfl_sync(0xffffffffu, acc[0][3], srcl);
        fz = (q & 1) ? vb : va;
        va = __shfl_sync(0xffffffffu, acc[1][0], srcl);
        vb = __shfl_sync(0xffffffffu, acc[1][1], srcl);
        gz = (q & 1) ? vb : va;
        va = __shfl_sync(0xffffffffu, acc[1][2], srcl);
        vb = __shfl_sync(0xffffffffu, acc[1][3], srcl);
        oz = (q & 1) ? vb : va;

        // ---- elementwise: ONE cell per lane ----
        float2 flo = __half22float2(*(__half2*)&xc.x);   // (i, f)
        float2 fhi = __half22float2(*(__half2*)&xc.y);   // (g, o)
        float iv = sigm(iz + flo.x);
        float fv = sigm(fz + flo.y);
        float gv = tanha(gz + fhi.x);
        float ov = sigm(oz + fhi.y);
        cst = fv * cst + iv * gv;
        float hv = ov * tanha(cst);
        __half hh = __float2half(hv);
        if (t + 1 < TT) *(__half*)(hp + (ph ^ 1) * 2048 + hoff) = hh;
        if (LAYER == 0) {
            g_hs[((size_t)t * BB + b0 + q) * UU + ut] = hh;
        } else if (t == TT - 1) {
            g_hlast[(size_t)(b0 + q) * UU + ut] = hv;
        }
        xc = xn;
        __syncthreads();   // hp[ph^1] complete for next step
        ph ^= 1;
    }
}

// ---------- dense ----------
__global__ void k_dense(const float* __restrict__ Wd, const float* __restrict__ bd,
                        float* __restrict__ out) {
    int b = blockIdx.x * blockDim.x + threadIdx.x;
    if (b >= BB) return;
    float acc = bd[0];
    const float* h = &g_hlast[(size_t)b * UU];
#pragma unroll 8
    for (int u = 0; u < UU; u++) acc = fmaf(h[u], Wd[u], acc);
    out[b] = fmaxf(acc, 0.f);
}

// ---------- launch ----------
extern "C" void kernel_launch(void* const* d_in, const int* in_sizes, int n_in,
                              void* d_out, int out_size) {
    const float* x  = (const float*)d_in[0];
    const float* W1 = (const float*)d_in[1];
    const float* U1 = (const float*)d_in[2];
    const float* b1 = (const float*)d_in[3];
    const float* W2 = (const float*)d_in[4];
    const float* U2 = (const float*)d_in[5];
    const float* b2 = (const float*)d_in[6];
    const float* Wd = (const float*)d_in[7];
    const float* bd = (const float*)d_in[8];
    float* out = (float*)d_out;

    const int SM_G64  = 32 * 136 * 4 + 2 * 64 * 72 * 2;     // 35840
    const int SM_G128 = 64 * 136 * 4 + 2 * 64 * 136 * 2;    // 69632
    const int SM_RNN  = 512 * 136 * 2 + 2 * 2048;           // 143360

    cudaFuncSetAttribute((const void*)k_gemm<64, true>,
                         cudaFuncAttributeMaxDynamicSharedMemorySize, SM_G64);
    cudaFuncSetAttribute((const void*)k_gemm<128, false>,
                         cudaFuncAttributeMaxDynamicSharedMemorySize, SM_G128);
    cudaFuncSetAttribute((const void*)k_rnn<0>,
                         cudaFuncAttributeMaxDynamicSharedMemorySize, SM_RNN);
    cudaFuncSetAttribute((const void*)k_rnn<1>,
                         cudaFuncAttributeMaxDynamicSharedMemorySize, SM_RNN);

    __half* xzp;   cudaGetSymbolAddress((void**)&xzp,  g_xz);
    __half* hsp;   cudaGetSymbolAddress((void**)&hsp,  g_hs);

    k_gemm<64, true><<<296, 256, SM_G64>>>(x, W1, b1, xzp, TB / 64);
    k_rnn<0><<<128, 512, SM_RNN>>>(U1);
    k_gemm<128, false><<<296, 256, SM_G128>>>(hsp, W2, b2, xzp, TB / 64);
    k_rnn<1><<<128, 512, SM_RNN>>>(U2);
    k_dense<<<4, 128>>>(Wd, bd, out);
}

// round 16
// speedup vs baseline: 1.5471x; 1.5471x over previous
#include <cuda_runtime.h>
#include <cuda_fp16.h>
#include <cstdint>

#define TT 256
#define BB 512
#define FF 64
#define UU 128
#define NG 512           // 4*U
#define TB (TT*BB)       // 131072

// ---------- static device scratch (no allocation) ----------
__device__ __half g_xz [(size_t)TB * NG];   // xz fp16, gate-interleaved [m][u*4+g]
__device__ __half g_hs [(size_t)TB * UU];   // layer-1 hidden states [t][b][u]
__device__ float  g_hlast[BB * UU];         // layer-2 final h

// ---------- helpers ----------
__device__ __forceinline__ void mma16816(float* d, const uint32_t* a, uint32_t b0, uint32_t b1) {
    asm volatile(
        "mma.sync.aligned.m16n8k16.row.col.f32.f16.f16.f32 "
        "{%0,%1,%2,%3}, {%4,%5,%6,%7}, {%8,%9}, {%0,%1,%2,%3};"
        : "+f"(d[0]), "+f"(d[1]), "+f"(d[2]), "+f"(d[3])
        : "r"(a[0]), "r"(a[1]), "r"(a[2]), "r"(a[3]), "r"(b0), "r"(b1));
}
__device__ __forceinline__ void ldsm4(uint32_t* a, const __half* p) {
    uint32_t addr = (uint32_t)__cvta_generic_to_shared(p);
    asm volatile("ldmatrix.sync.aligned.m8n8.x4.shared.b16 {%0,%1,%2,%3}, [%4];"
                 : "=r"(a[0]), "=r"(a[1]), "=r"(a[2]), "=r"(a[3]) : "r"(addr));
}
__device__ __forceinline__ float tanha(float x) {
    float r;
    asm("tanh.approx.f32 %0, %1;" : "=f"(r) : "f"(x));
    return r;
}
__device__ __forceinline__ float sigm(float x) {
    return fmaf(0.5f, tanha(0.5f * x), 0.5f);
}

// ---------- GEMM: out16[M][perm(512)] = A @ W(fp32->fp16) + bias ----------
// Physical output col P holds logical gate-col l = (P&3)*128 + (P>>2), i.e.
// out[m][u*4+g]. Permutation applied at Wp/bias GATHER (free); stores remain
// coalesced half2. Software-pipelined: double-buffered As, ONE barrier/tile.
// DX=true: A is raw x fp32 [b][t][f] (K=64).
template <int K, bool DX>
__global__ void __launch_bounds__(256, 2)
k_gemm(const void* __restrict__ Av, const float* __restrict__ Wg,
       const float* __restrict__ bias, __half* __restrict__ out, int Mtiles) {
    extern __shared__ char sm[];
    const int NT = 128, LDW = 136, ldA = K + 8;
    uint32_t* Wp = (uint32_t*)sm;                                  // [K/2][136] half2
    __half*   As = (__half*)(sm + (K / 2) * LDW * 4);              // [2][64][K+8]
    const int ABUF = 64 * ldA;
    int tid = threadIdx.x, w = tid >> 5, lane = tid & 31;
    int n0 = (blockIdx.x & 3) * NT;
    int tile0 = blockIdx.x >> 2, tstep = gridDim.x >> 2;

    for (int i = tid; i < (K / 2) * NT; i += 256) {
        int kk = i >> 7, nl = i & 127;
        int P = n0 + nl;
        int l = (P & 3) * 128 + (P >> 2);        // gate-interleave permutation
        __half2 h2 = __floats2half2_rn(Wg[(size_t)(2 * kk) * NG + l],
                                       Wg[(size_t)(2 * kk + 1) * NG + l]);
        Wp[kk * LDW + nl] = *(uint32_t*)&h2;
    }

    float4 stg[4];
    auto ldtile = [&](int m0) {
#pragma unroll
        for (int s = 0; s < 4; s++) {
            int i = tid + 256 * s;
            int r = i >> 4;
            if (DX) {
                int c = (i & 15) * 4;
                int m = m0 + r, t = m >> 9, b = m & 511;
                stg[s] = *(const float4*)&((const float*)Av)[((size_t)(b << 8 | t)) * FF + c];
            } else {
                int c = (i & 15) * 8;
                stg[s] = *(const float4*)&((const __half*)Av)[(size_t)(m0 + r) * K + c];
            }
        }
    };
    auto sttile = [&](int buf) {
#pragma unroll
        for (int s = 0; s < 4; s++) {
            int i = tid + 256 * s;
            int r = i >> 4;
            if (DX) {
                int c = (i & 15) * 4;
                *(__half2*)&As[buf * ABUF + r * ldA + c]     = __floats2half2_rn(stg[s].x, stg[s].y);
                *(__half2*)&As[buf * ABUF + r * ldA + c + 2] = __floats2half2_rn(stg[s].z, stg[s].w);
            } else {
                int c = (i & 15) * 8;
                *(float4*)&As[buf * ABUF + r * ldA + c] = stg[s];
            }
        }
    };

    int cur = 0;
    ldtile(tile0 * 64);
    sttile(0);
    __syncthreads();

    for (int tile = tile0; tile < Mtiles; tile += tstep) {
        int m0 = tile * 64;
        bool havenext = (tile + tstep < Mtiles);
        if (havenext) ldtile((tile + tstep) * 64);

        float acc[4][2][4];
#pragma unroll
        for (int mt = 0; mt < 4; mt++)
#pragma unroll
            for (int nt = 0; nt < 2; nt++)
#pragma unroll
                for (int q = 0; q < 4; q++) acc[mt][nt][q] = 0.f;

        const __half* Ac = As + cur * ABUF;
#pragma unroll
        for (int kt = 0; kt < K / 16; kt++) {
            uint32_t a[4][4];
#pragma unroll
            for (int mt = 0; mt < 4; mt++) {
                int row = mt * 16 + (lane & 15);
                int col = kt * 16 + (lane >> 4) * 8;
                ldsm4(a[mt], &Ac[row * ldA + col]);
            }
            int c4 = lane & 3;
#pragma unroll
            for (int nt = 0; nt < 2; nt++) {
                int nl = w * 16 + nt * 8 + (lane >> 2);
                uint32_t b0 = Wp[(kt * 8 + c4) * LDW + nl];
                uint32_t b1 = Wp[(kt * 8 + 4 + c4) * LDW + nl];
#pragma unroll
                for (int mt = 0; mt < 4; mt++) mma16816(acc[mt][nt], a[mt], b0, b1);
            }
        }

#pragma unroll
        for (int mt = 0; mt < 4; mt++) {
            int r0 = m0 + mt * 16 + (lane >> 2);
#pragma unroll
            for (int nt = 0; nt < 2; nt++) {
                int cc = n0 + w * 16 + nt * 8 + (lane & 3) * 2;
                int l0 = (cc & 3) * 128 + (cc >> 2);
                int l1 = ((cc + 1) & 3) * 128 + ((cc + 1) >> 2);
                float bb0 = __ldg(&bias[l0]), bb1 = __ldg(&bias[l1]);
                *(__half2*)&out[(size_t)r0 * NG + cc] =
                    __floats2half2_rn(acc[mt][nt][0] + bb0, acc[mt][nt][1] + bb1);
                *(__half2*)&out[(size_t)(r0 + 8) * NG + cc] =
                    __floats2half2_rn(acc[mt][nt][2] + bb0, acc[mt][nt][3] + bb1);
            }
        }

        if (havenext) sttile(cur ^ 1);
        __syncthreads();
        cur ^= 1;
    }
}

// ---------- LSTM recurrence ----------
// 128 CTAs x 4 batches, 512 threads (16 warps). Warp w owns units [w*8, w*8+8)
// with 2 m16-tiles: tile mt -> gates {2mt, 2mt+1}. Split even/odd-kt
// accumulators, STATIC kt indexing (A fragments must stay in registers!).
// n>=4 B-fragments are structurally zero -> lanes 16-31 skip the hp LDS
// (predicated, no divergent control flow). ONE barrier per step.
template <int LAYER>
__global__ void __launch_bounds__(512, 1)
k_rnn(const float* __restrict__ Urec) {
    extern __shared__ char sm[];
    __half* As = (__half*)sm;                        // [512][136] = 139264 B
    char*   hp = sm + 512 * 136 * 2;                 // 2 phases x 2048 B
    const int th = threadIdx.x, w = th >> 5, lane = th & 31;
    const int b0 = blockIdx.x * 4;

    // stage permuted U^T: row = w*32 + mt*16 + sub*8 + r -> G = (2mt+sub)*128 + w*8 + r
    for (int i = th; i < 512 * 128; i += 512) {
        int row = i >> 7, k = i & 127;
        int ww = row >> 5, mt = (row >> 4) & 1, sub = (row >> 3) & 1, r = row & 7;
        int G = (2 * mt + sub) * 128 + ww * 8 + r;
        As[row * 136 + k] = __float2half(Urec[(size_t)k * NG + G]);
    }
    for (int i = th; i < 1024; i += 512) ((uint32_t*)hp)[i] = 0u;
    __syncthreads();

    uint32_t ua[2][8][4];
#pragma unroll
    for (int mt = 0; mt < 2; mt++) {
        int row = w * 32 + mt * 16 + (lane & 15);
#pragma unroll
        for (int kt = 0; kt < 8; kt++)
            ldsm4(ua[mt][kt], &As[row * 136 + kt * 16 + (lane >> 4) * 8]);
    }
    __syncthreads();

    const int q  = lane & 3, r8 = lane >> 2;
    const int ut = w * 8 + r8;                      // this lane's unit
    const int srcl = (lane & 28) | (q >> 1);        // shfl source lane
    const int hoff = (ut >> 4) * 256 + ((ut & 7) >> 1) * 64 + q * 8
                   + ((ut >> 3) & 1) * 4 + (ut & 1) * 2;
    const bool bload = (lane < 16);                 // n>=4 fragments are zero

    // xz gate-interleaved: one 8-byte load = 4 gates (i,f,g,o) fp16
    uint2 xc = *(const uint2*)&g_xz[((size_t)(b0 + q)) * NG + ut * 4];
    float cst = 0.f;
    int ph = 0;

    for (int t = 0; t < TT; t++) {
        // ---- mma: z = U^T @ h^T (reads hp[ph]); even/odd split chains ----
        float ae[2][4], ao[2][4];
#pragma unroll
        for (int mt = 0; mt < 2; mt++)
#pragma unroll
            for (int j = 0; j < 4; j++) { ae[mt][j] = 0.f; ao[mt][j] = 0.f; }
        const char* hpc = hp + ph * 2048;
#pragma unroll
        for (int kt = 0; kt < 8; kt++) {
            uint2 bf = make_uint2(0u, 0u);
            if (bload)
                bf = *(const uint2*)(hpc + kt * 256 + (lane & 3) * 64 + (lane >> 2) * 8);
            float* d0 = (kt & 1) ? ao[0] : ae[0];
            float* d1 = (kt & 1) ? ao[1] : ae[1];
            mma16816(d0, ua[0][kt], bf.x, bf.y);
            mma16816(d1, ua[1][kt], bf.x, bf.y);
        }
        float acc[2][4];
#pragma unroll
        for (int mt = 0; mt < 2; mt++)
#pragma unroll
            for (int j = 0; j < 4; j++) acc[mt][j] = ae[mt][j] + ao[mt][j];

        // prefetch next step's xz (one 8B load)
        uint2 xn = xc;
        if (t + 1 < TT)
            xn = *(const uint2*)&g_xz[((size_t)(t + 1) * BB + b0 + q) * NG + ut * 4];

        // ---- gate extraction: 8 shfl + 4 selects ----
        float va, vb, iz, fz, gz, oz;
        va = __shfl_sync(0xffffffffu, acc[0][0], srcl);
        vb = __shfl_sync(0xffffffffu, acc[0][1], srcl);
        iz = (q & 1) ? vb : va;
        va = __shfl_sync(0xffffffffu, acc[0][2], srcl);
        vb = __shfl_sync(0xffffffffu, acc[0][3], srcl);
        fz = (q & 1) ? vb : va;
        va = __shfl_sync(0xffffffffu, acc[1][0], srcl);
        vb = __shfl_sync(0xffffffffu, acc[1][1], srcl);
        gz = (q & 1) ? vb : va;
        va = __shfl_sync(0xffffffffu, acc[1][2], srcl);
        vb = __shfl_sync(0xffffffffu, acc[1][3], srcl);
        oz = (q & 1) ? vb : va;

        // ---- elementwise: ONE cell per lane ----
        float2 flo = __half22float2(*(__half2*)&xc.x);   // (i, f)
        float2 fhi = __half22float2(*(__half2*)&xc.y);   // (g, o)
        float iv = sigm(iz + flo.x);
        float fv = sigm(fz + flo.y);
        float gv = tanha(gz + fhi.x);
        float ov = sigm(oz + fhi.y);
        cst = fv * cst + iv * gv;
        float hv = ov * tanha(cst);
        __half hh = __float2half(hv);
        if (t + 1 < TT) *(__half*)(hp + (ph ^ 1) * 2048 + hoff) = hh;
        if (LAYER == 0) {
            g_hs[((size_t)t * BB + b0 + q) * UU + ut] = hh;
        } else if (t == TT - 1) {
            g_hlast[(size_t)(b0 + q) * UU + ut] = hv;
        }
        xc = xn;
        __syncthreads();   // hp[ph^1] complete for next step
        ph ^= 1;
    }
}

// ---------- dense ----------
__global__ void k_dense(const float* __restrict__ Wd, const float* __restrict__ bd,
                        float* __restrict__ out) {
    int b = blockIdx.x * blockDim.x + threadIdx.x;
    if (b >= BB) return;
    float acc = bd[0];
    const float* h = &g_hlast[(size_t)b * UU];
#pragma unroll 8
    for (int u = 0; u < UU; u++) acc = fmaf(h[u], Wd[u], acc);
    out[b] = fmaxf(acc, 0.f);
}

// ---------- launch ----------
extern "C" void kernel_launch(void* const* d_in, const int* in_sizes, int n_in,
                              void* d_out, int out_size) {
    const float* x  = (const float*)d_in[0];
    const float* W1 = (const float*)d_in[1];
    const float* U1 = (const float*)d_in[2];
    const float* b1 = (const float*)d_in[3];
    const float* W2 = (const float*)d_in[4];
    const float* U2 = (const float*)d_in[5];
    const float* b2 = (const float*)d_in[6];
    const float* Wd = (const float*)d_in[7];
    const float* bd = (const float*)d_in[8];
    float* out = (float*)d_out;

    const int SM_G64  = 32 * 136 * 4 + 2 * 64 * 72 * 2;     // 35840
    const int SM_G128 = 64 * 136 * 4 + 2 * 64 * 136 * 2;    // 69632
    const int SM_RNN  = 512 * 136 * 2 + 2 * 2048;           // 143360

    cudaFuncSetAttribute((const void*)k_gemm<64, true>,
                         cudaFuncAttributeMaxDynamicSharedMemorySize, SM_G64);
    cudaFuncSetAttribute((const void*)k_gemm<128, false>,
                         cudaFuncAttributeMaxDynamicSharedMemorySize, SM_G128);
    cudaFuncSetAttribute((const void*)k_rnn<0>,
                         cudaFuncAttributeMaxDynamicSharedMemorySize, SM_RNN);
    cudaFuncSetAttribute((const void*)k_rnn<1>,
                         cudaFuncAttributeMaxDynamicSharedMemorySize, SM_RNN);

    __half* xzp;   cudaGetSymbolAddress((void**)&xzp,  g_xz);
    __half* hsp;   cudaGetSymbolAddress((void**)&hsp,  g_hs);

    k_gemm<64, true><<<296, 256, SM_G64>>>(x, W1, b1, xzp, TB / 64);
    k_rnn<0><<<128, 512, SM_RNN>>>(U1);
    k_gemm<128, false><<<296, 256, SM_G128>>>(hsp, W2, b2, xzp, TB / 64);
    k_rnn<1><<<128, 512, SM_RNN>>>(U2);
    k_dense<<<4, 128>>>(Wd, bd, out);
}